// round 2
// baseline (speedup 1.0000x reference)
#include <cuda_runtime.h>
#include <cuda_fp16.h>
#include <mma.h>

using namespace nvcuda;

#define NN 512
#define DD 256
#define HH 256
#define EE 128

// ---------------- static device scratch ----------------
__device__ __align__(128) float  g_s[NN * DD];
__device__ __align__(128) __half g_qh[NN * HH];
__device__ __align__(128) __half g_kh[NN * HH];
__device__ __align__(128) __half g_wpT[HH * EE];    // [h][e]
__device__ __align__(128) float  g_aq[NN * EE];     // q @ w_d^T
__device__ __align__(128) float  g_bkp[NN * EE];    // o_b - k @ w_d^T

// ---------------- LayerNorm: one block per node row ----------------
__global__ __launch_bounds__(256) void k_ln(const float* __restrict__ node,
                                            const float* __restrict__ lw,
                                            const float* __restrict__ lb) {
    int j = blockIdx.x, t = threadIdx.x;
    __shared__ float red[8];
    float v = node[j * DD + t];
    float x = v;
    #pragma unroll
    for (int o = 16; o > 0; o >>= 1) x += __shfl_xor_sync(0xffffffffu, x, o);
    if ((t & 31) == 0) red[t >> 5] = x;
    __syncthreads();
    float mu = 0.f;
    #pragma unroll
    for (int w = 0; w < 8; w++) mu += red[w];
    mu *= (1.0f / 256.0f);
    __syncthreads();
    float d = v - mu;
    x = d * d;
    #pragma unroll
    for (int o = 16; o > 0; o >>= 1) x += __shfl_xor_sync(0xffffffffu, x, o);
    if ((t & 31) == 0) red[t >> 5] = x;
    __syncthreads();
    float var = 0.f;
    #pragma unroll
    for (int w = 0; w < 8; w++) var += red[w];
    var *= (1.0f / 256.0f);
    float rs = rsqrtf(var + 1e-5f);
    g_s[j * DD + t] = d * rs * lw[t] + lb[t];
}

// ---------------- transpose w_p (= o_w[:, :256]) into fp16 [h][e] ----------------
__global__ __launch_bounds__(256) void k_wp(const float* __restrict__ ow) {
    int idx = blockIdx.x * 256 + threadIdx.x;       // 0..32767
    int h = idx >> 7, e = idx & 127;
    g_wpT[h * EE + e] = __float2half(ow[e * (2 * HH) + h]);
}

// ---------------- proj GEMM: [512,256] @ [256,512] -> g_qh/g_kh fp16 ----------------
__global__ __launch_bounds__(128) void k_proj(const float* __restrict__ pw,
                                              const float* __restrict__ pb) {
    __shared__ float sAt[64][36];
    __shared__ float sBt[64][68];
    int t = threadIdx.x;
    int j0 = blockIdx.x * 32;
    int h0 = blockIdx.y * 64;
    int ty = t >> 4;
    int tx = t & 15;
    float acc[4][4] = {};
    for (int kc = 0; kc < DD; kc += 64) {
        __syncthreads();
        {
            int r = t >> 2;
            int c0 = (t & 3) * 16;
            const float* src = g_s + (j0 + r) * DD + kc + c0;
            #pragma unroll
            for (int u = 0; u < 16; u += 4) {
                float4 v = *(const float4*)(src + u);
                sAt[c0 + u + 0][r] = v.x; sAt[c0 + u + 1][r] = v.y;
                sAt[c0 + u + 2][r] = v.z; sAt[c0 + u + 3][r] = v.w;
            }
        }
        {
            int r = t >> 1;
            int c0 = (t & 1) * 32;
            const float* src = pw + (h0 + r) * DD + kc + c0;
            #pragma unroll
            for (int u = 0; u < 32; u += 4) {
                float4 v = *(const float4*)(src + u);
                sBt[c0 + u + 0][r] = v.x; sBt[c0 + u + 1][r] = v.y;
                sBt[c0 + u + 2][r] = v.z; sBt[c0 + u + 3][r] = v.w;
            }
        }
        __syncthreads();
        #pragma unroll 8
        for (int k = 0; k < 64; k++) {
            float4 a = *(const float4*)&sAt[k][ty * 4];
            float4 b = *(const float4*)&sBt[k][tx * 4];
            float av[4] = {a.x, a.y, a.z, a.w};
            float bv[4] = {b.x, b.y, b.z, b.w};
            #pragma unroll
            for (int m = 0; m < 4; m++)
                #pragma unroll
                for (int n = 0; n < 4; n++)
                    acc[m][n] += av[m] * bv[n];
        }
    }
    #pragma unroll
    for (int m = 0; m < 4; m++) {
        int j = j0 + ty * 4 + m;
        #pragma unroll
        for (int n = 0; n < 4; n++) {
            int h = h0 + tx * 4 + n;
            __half hv = __float2half(acc[m][n] + pb[h]);
            if (h < HH) g_qh[j * HH + h] = hv;
            else        g_kh[j * HH + (h - HH)] = hv;
        }
    }
}

// ---------------- Aq / Bk' GEMM: [q;k](1024x256) @ w_d^T(256x128) ----------------
__global__ __launch_bounds__(128) void k_aqbk(const float* __restrict__ ow,
                                              const float* __restrict__ ob) {
    __shared__ float sAt[64][20];
    __shared__ float sBt[64][68];
    int t = threadIdx.x;
    int m0 = blockIdx.x * 16;
    int e0 = blockIdx.y * 64;
    int ty = t >> 4;
    int tx = t & 15;
    float acc[2][4] = {};
    for (int kc = 0; kc < HH; kc += 64) {
        __syncthreads();
        {
            int r = t >> 3;
            int c0 = (t & 7) * 8;
            int gr = m0 + r;
            const __half* src = (gr < NN) ? (g_qh + (size_t)gr * HH)
                                          : (g_kh + (size_t)(gr - NN) * HH);
            src += kc + c0;
            #pragma unroll
            for (int u = 0; u < 8; u++) sAt[c0 + u][r] = __half2float(src[u]);
        }
        {
            int r = t >> 1;
            int c0 = (t & 1) * 32;
            const float* src = ow + (e0 + r) * (2 * HH) + HH + kc + c0;
            #pragma unroll
            for (int u = 0; u < 32; u += 4) {
                float4 v = *(const float4*)(src + u);
                sBt[c0 + u + 0][r] = v.x; sBt[c0 + u + 1][r] = v.y;
                sBt[c0 + u + 2][r] = v.z; sBt[c0 + u + 3][r] = v.w;
            }
        }
        __syncthreads();
        #pragma unroll 8
        for (int k = 0; k < 64; k++) {
            float2 a = *(const float2*)&sAt[k][ty * 2];
            float4 b = *(const float4*)&sBt[k][tx * 4];
            float av[2] = {a.x, a.y};
            float bv[4] = {b.x, b.y, b.z, b.w};
            #pragma unroll
            for (int m = 0; m < 2; m++)
                #pragma unroll
                for (int n = 0; n < 4; n++)
                    acc[m][n] += av[m] * bv[n];
        }
    }
    #pragma unroll
    for (int m = 0; m < 2; m++) {
        int gr = m0 + ty * 2 + m;
        #pragma unroll
        for (int n = 0; n < 4; n++) {
            int e = e0 + tx * 4 + n;
            if (gr < NN) g_aq[gr * EE + e] = acc[m][n];
            else         g_bkp[(size_t)(gr - NN) * EE + e] = ob[e] - acc[m][n];
        }
    }
}

// ---------------- main: per i, T = (q .* k_i) @ w_p^T, fused epilogue ----------------
#define TJ 128
#define TI 4
#define LDQ 272                     // halfs per row (256 + 16 pad)
#define LDW 144                     // halfs per row (128 + 16 pad)
#define SM_Q 0
#define SM_B (128 * LDQ * 2)        // 69632
#define SM_A (SM_B + 256 * LDW * 2) // 143360
#define SM_K (SM_A + 128 * LDQ * 2) // 212992
#define SM_BK (SM_K + 512)          // 213504
#define SMEM_MAIN (SM_BK + 16 * 128 * 4)  // 221696

__global__ __launch_bounds__(256, 1) void k_main(float* __restrict__ out) {
    extern __shared__ char smem_raw[];
    __half* sQ  = (__half*)(smem_raw + SM_Q);
    __half* sB  = (__half*)(smem_raw + SM_B);
    __half* sA  = (__half*)(smem_raw + SM_A);
    __half* sK  = (__half*)(smem_raw + SM_K);
    float*  sBk = (float*)(smem_raw + SM_BK);

    int t = threadIdx.x;
    int w = t >> 5;
    int wj = w >> 1;                 // 0..3
    int we = w & 1;                  // 0..1
    int j0 = blockIdx.x * TJ;
    int ibase = blockIdx.y * TI;

    // q tile: 128 rows x 256 halfs
    for (int idx = t; idx < 4096; idx += 256) {
        int r = idx >> 5, c = idx & 31;
        *(int4*)(sQ + r * LDQ + c * 8) = *(const int4*)(g_qh + (size_t)(j0 + r) * HH + c * 8);
    }
    // w_p^T tile: 256 rows x 128 halfs
    for (int idx = t; idx < 4096; idx += 256) {
        int r = idx >> 4, c = idx & 15;
        *(int4*)(sB + r * LDW + c * 8) = *(const int4*)(g_wpT + (size_t)r * EE + c * 8);
    }

    for (int it = 0; it < TI; it++) {
        int i = ibase + it;
        // k row
        if (t < 32) *(int4*)(sK + t * 8) = *(const int4*)(g_kh + (size_t)i * HH + t * 8);
        // replicated (o_b - Bk[i]) rows: 16 x 128 f32
        {
            const float4* src = (const float4*)(g_bkp + (size_t)i * EE);
            #pragma unroll
            for (int idx = t; idx < 512; idx += 256) {
                int c = idx & 31;
                ((float4*)sBk)[idx] = src[c];
            }
        }
        __syncthreads();

        // A' = q .* k_i
        for (int idx = t; idx < 4096; idx += 256) {
            int r = idx >> 5, c = idx & 31;
            int4 qv = *(const int4*)(sQ + r * LDQ + c * 8);
            int4 kv = *(const int4*)(sK + c * 8);
            const __half2* qh = (const __half2*)&qv;
            const __half2* kh = (const __half2*)&kv;
            int4 av;
            __half2* ah = (__half2*)&av;
            ah[0] = __hmul2(qh[0], kh[0]);
            ah[1] = __hmul2(qh[1], kh[1]);
            ah[2] = __hmul2(qh[2], kh[2]);
            ah[3] = __hmul2(qh[3], kh[3]);
            *(int4*)(sA + r * LDQ + c * 8) = av;
        }
        __syncthreads();

        wmma::fragment<wmma::accumulator, 16, 16, 16, float> acc[2][4];
        #pragma unroll
        for (int m = 0; m < 2; m++)
            #pragma unroll
            for (int n = 0; n < 4; n++)
                wmma::fill_fragment(acc[m][n], 0.0f);

        #pragma unroll
        for (int kk = 0; kk < HH; kk += 16) {
            wmma::fragment<wmma::matrix_a, 16, 16, 16, __half, wmma::row_major> af[2];
            wmma::fragment<wmma::matrix_b, 16, 16, 16, __half, wmma::row_major> bf[4];
            #pragma unroll
            for (int m = 0; m < 2; m++)
                wmma::load_matrix_sync(af[m], sA + (wj * 32 + m * 16) * LDQ + kk, LDQ);
            #pragma unroll
            for (int n = 0; n < 4; n++)
                wmma::load_matrix_sync(bf[n], sB + kk * LDW + we * 64 + n * 16, LDW);
            #pragma unroll
            for (int m = 0; m < 2; m++)
                #pragma unroll
                for (int n = 0; n < 4; n++)
                    wmma::mma_sync(acc[m][n], af[m], bf[n], acc[m][n]);
        }

        // epilogue: + Aq[j,e] + (o_b - Bk[i])[e], store
        #pragma unroll
        for (int m = 0; m < 2; m++) {
            int jr = j0 + wj * 32 + m * 16;
            #pragma unroll
            for (int n = 0; n < 4; n++) {
                int ec = we * 64 + n * 16;
                wmma::fragment<wmma::accumulator, 16, 16, 16, float> aqf, bkf;
                wmma::load_matrix_sync(aqf, g_aq + (size_t)jr * EE + ec, EE, wmma::mem_row_major);
                wmma::load_matrix_sync(bkf, sBk + ec, 128, wmma::mem_row_major);
                #pragma unroll
                for (int u = 0; u < acc[m][n].num_elements; u++)
                    acc[m][n].x[u] += aqf.x[u] + bkf.x[u];
                wmma::store_matrix_sync(out + ((size_t)i * NN + jr) * EE + ec,
                                        acc[m][n], EE, wmma::mem_row_major);
            }
        }
        __syncthreads();
    }
}

// ---------------- launcher ----------------
extern "C" void kernel_launch(void* const* d_in, const int* in_sizes, int n_in,
                              void* d_out, int out_size) {
    const float* node = (const float*)d_in[0];
    const float* ln_w = (const float*)d_in[1];
    const float* ln_b = (const float*)d_in[2];
    const float* pw   = (const float*)d_in[3];
    const float* pb   = (const float*)d_in[4];
    const float* ow   = (const float*)d_in[5];
    const float* ob   = (const float*)d_in[6];
    float* out = (float*)d_out;

    cudaFuncSetAttribute(k_main, cudaFuncAttributeMaxDynamicSharedMemorySize, SMEM_MAIN);

    k_ln<<<NN, 256>>>(node, ln_w, ln_b);
    k_wp<<<128, 256>>>(ow);
    {
        dim3 g(NN / 32, (2 * HH) / 64);
        k_proj<<<g, 128>>>(pw, pb);
    }
    {
        dim3 g((2 * NN) / 16, EE / 64);
        k_aqbk<<<g, 128>>>(ow, ob);
    }
    {
        dim3 g(NN / TJ, NN / TI);
        k_main<<<g, 256, SMEM_MAIN>>>(out);
    }
}

// round 4
// speedup vs baseline: 1.7347x; 1.7347x over previous
#include <cuda_runtime.h>
#include <cuda_fp16.h>
#include <mma.h>
#include <cstdint>

#define NN 512
#define DD 256
#define HH 256
#define EE 128
#define TJ 128
#define TI 16

// Arch-specific (sm_103a) pass detection: tcgen05 only exists there.
#if defined(__CUDA_ARCH__) && (defined(__CUDA_ARCH_FEAT_SM103_ALL) || defined(__CUDA_ARCH_FEAT_SM100_ALL) || defined(__CUDA_ARCH_SPECIFIC__))
#define HAS_TCGEN05 1
#else
#define HAS_TCGEN05 0
#endif

// ---------------- static device scratch ----------------
__device__ __align__(128) float  g_s[NN * DD];
__device__ __align__(128) __half g_qh[NN * HH];     // q fp16 [j][h]
__device__ __align__(128) __half g_kh[NN * HH];     // k fp16 [i][h]
__device__ __align__(128) __half g_wpB[HH * EE];    // w_p SW128 blocked-atom image [e rows][h cols]
__device__ __align__(128) __half g_wpT[HH * EE];    // w_p transposed linear [h][e] (wmma fallback)
__device__ __align__(128) float  g_aq[NN * EE];     // q @ w_d^T
__device__ __align__(128) float  g_bkp[NN * EE];    // o_b - k @ w_d^T

// ---------------- PTX helpers ----------------
__device__ __forceinline__ uint32_t smem_u32(const void* p) {
    uint32_t a;
    asm("{ .reg .u64 t; cvta.to.shared.u64 t, %1; cvt.u32.u64 %0, t; }" : "=r"(a) : "l"(p));
    return a;
}

#if HAS_TCGEN05
__device__ __forceinline__ uint32_t elect_one() {
    uint32_t p;
    asm volatile("{ .reg .pred p; elect.sync _|p, 0xFFFFFFFF; selp.b32 %0, 1, 0, p; }" : "=r"(p));
    return p;
}
#define TC_ALLOC(dst, n) \
    asm volatile("tcgen05.alloc.cta_group::1.sync.aligned.shared::cta.b32 [%0], %1;" \
                 :: "r"(dst), "r"(n) : "memory")
#define TC_RELINQ() \
    asm volatile("tcgen05.relinquish_alloc_permit.cta_group::1.sync.aligned;")
#define TC_DEALLOC(base, n) \
    asm volatile("tcgen05.dealloc.cta_group::1.sync.aligned.b32 %0, %1;" :: "r"(base), "r"(n))
#define TC_WAIT_ST() asm volatile("tcgen05.wait::st.sync.aligned;" ::: "memory")
#define TC_WAIT_LD() asm volatile("tcgen05.wait::ld.sync.aligned;" ::: "memory")
#define TC_FENCE_BEFORE() asm volatile("tcgen05.fence::before_thread_sync;" ::: "memory")
#define TC_FENCE_AFTER()  asm volatile("tcgen05.fence::after_thread_sync;" ::: "memory")
#define TC_COMMIT(mbar) \
    asm volatile("tcgen05.commit.cta_group::1.mbarrier::arrive::one.shared::cluster.b64 [%0];" \
                 :: "r"(mbar) : "memory")
#define MBAR_INIT(a, c) \
    asm volatile("mbarrier.init.shared.b64 [%0], %1;" :: "r"(a), "r"(c) : "memory")
#define MBAR_ARRIVE(a) \
    asm volatile("mbarrier.arrive.shared.b64 _, [%0];" :: "r"(a) : "memory")
#define MBAR_INVAL(a) \
    asm volatile("mbarrier.inval.shared.b64 [%0];" :: "r"(a) : "memory")

#define MBAR_WAIT(mbar, par) do {                                              \
    uint32_t _m = (mbar), _p = (par), _d;                                      \
    asm volatile("{ .reg .pred p; mbarrier.try_wait.parity.acquire.cta.shared::cta.b64 p, [%1], %2; selp.b32 %0, 1, 0, p; }" \
        : "=r"(_d) : "r"(_m), "r"(_p) : "memory");                             \
    if (!_d) {                                                                 \
        asm volatile("{ .reg .pred P1; WL_%=: mbarrier.try_wait.parity.acquire.cta.shared::cta.b64 P1, [%0], %1, 0x989680; @P1 bra.uni WD_%=; bra.uni WL_%=; WD_%=: }" \
            :: "r"(_m), "r"(_p) : "memory");                                   \
    }                                                                          \
} while (0)

#define TC_ST_X32(addr, r)                                                     \
    asm volatile("tcgen05.st.sync.aligned.32x32b.x32.b32 [%0], "               \
        "{%1,%2,%3,%4,%5,%6,%7,%8,%9,%10,%11,%12,%13,%14,%15,%16,"            \
        "%17,%18,%19,%20,%21,%22,%23,%24,%25,%26,%27,%28,%29,%30,%31,%32};"    \
        :: "r"(addr),                                                          \
        "r"((r)[0]),"r"((r)[1]),"r"((r)[2]),"r"((r)[3]),"r"((r)[4]),"r"((r)[5]),"r"((r)[6]),"r"((r)[7]), \
        "r"((r)[8]),"r"((r)[9]),"r"((r)[10]),"r"((r)[11]),"r"((r)[12]),"r"((r)[13]),"r"((r)[14]),"r"((r)[15]), \
        "r"((r)[16]),"r"((r)[17]),"r"((r)[18]),"r"((r)[19]),"r"((r)[20]),"r"((r)[21]),"r"((r)[22]),"r"((r)[23]), \
        "r"((r)[24]),"r"((r)[25]),"r"((r)[26]),"r"((r)[27]),"r"((r)[28]),"r"((r)[29]),"r"((r)[30]),"r"((r)[31]) \
        : "memory")

#define TC_LD_X32(r, addr)                                                     \
    asm volatile("tcgen05.ld.sync.aligned.32x32b.x32.b32 "                     \
        "{%0,%1,%2,%3,%4,%5,%6,%7,%8,%9,%10,%11,%12,%13,%14,%15,"             \
        "%16,%17,%18,%19,%20,%21,%22,%23,%24,%25,%26,%27,%28,%29,%30,%31}, [%32];" \
        : "=r"((r)[0]),"=r"((r)[1]),"=r"((r)[2]),"=r"((r)[3]),"=r"((r)[4]),"=r"((r)[5]),"=r"((r)[6]),"=r"((r)[7]), \
          "=r"((r)[8]),"=r"((r)[9]),"=r"((r)[10]),"=r"((r)[11]),"=r"((r)[12]),"=r"((r)[13]),"=r"((r)[14]),"=r"((r)[15]), \
          "=r"((r)[16]),"=r"((r)[17]),"=r"((r)[18]),"=r"((r)[19]),"=r"((r)[20]),"=r"((r)[21]),"=r"((r)[22]),"=r"((r)[23]), \
          "=r"((r)[24]),"=r"((r)[25]),"=r"((r)[26]),"=r"((r)[27]),"=r"((r)[28]),"=r"((r)[29]),"=r"((r)[30]),"=r"((r)[31]) \
        : "r"(addr))

#define TC_MMA_F16(d, a, bd, id, en) do {                                      \
    uint32_t _e = (en);                                                        \
    asm volatile("{ .reg .pred p; setp.ne.u32 p, %4, 0;"                       \
        " tcgen05.mma.cta_group::1.kind::f16 [%0], [%1], %2, %3, {%5,%5,%5,%5}, p; }" \
        :: "r"(d), "r"(a), "l"(bd), "r"(id), "r"(_e), "r"(0u) : "memory");     \
} while (0)

__device__ __forceinline__ uint64_t make_desc(uint32_t a) {
    const uint64_t base = (2ull << 61) | (1ull << 46) | (64ull << 32) | (1ull << 16);
    return base | ((uint64_t)(a >> 4) & 0x3FFF);
}
// idesc: F32 accum (bit4), atype=F16(0), btype=F16(0), N=128 (16<<17), M=128 (8<<24)
#define IDESC 0x8200010u
#endif  // HAS_TCGEN05

// ---------------- prep: LayerNorm ----------------
__global__ __launch_bounds__(256) void k_ln(const float* __restrict__ node,
                                            const float* __restrict__ lw,
                                            const float* __restrict__ lb) {
    int j = blockIdx.x, t = threadIdx.x;
    __shared__ float red[8];
    float v = node[j * DD + t];
    float x = v;
    #pragma unroll
    for (int o = 16; o > 0; o >>= 1) x += __shfl_xor_sync(0xffffffffu, x, o);
    if ((t & 31) == 0) red[t >> 5] = x;
    __syncthreads();
    float mu = 0.f;
    #pragma unroll
    for (int w = 0; w < 8; w++) mu += red[w];
    mu *= (1.0f / 256.0f);
    __syncthreads();
    float d = v - mu;
    x = d * d;
    #pragma unroll
    for (int o = 16; o > 0; o >>= 1) x += __shfl_xor_sync(0xffffffffu, x, o);
    if ((t & 31) == 0) red[t >> 5] = x;
    __syncthreads();
    float var = 0.f;
    #pragma unroll
    for (int w = 0; w < 8; w++) var += red[w];
    var *= (1.0f / 256.0f);
    float rs = rsqrtf(var + 1e-5f);
    g_s[j * DD + t] = d * rs * lw[t] + lb[t];
}

// ---------------- prep: w_p -> SW128 blocked-atom image + linear transpose ----------------
__global__ __launch_bounds__(256) void k_wp(const float* __restrict__ ow) {
    int idx = blockIdx.x * 256 + threadIdx.x;   // 0..32767
    int e = idx >> 8, h = idx & 255;
    __half v = __float2half(ow[e * (2 * HH) + h]);
    uint32_t off = (uint32_t)(((h >> 6) * 16 + (e >> 3)) * 1024 + (e & 7) * 128 + (h & 63) * 2);
    off ^= (off >> 3) & 0x70;
    g_wpB[off >> 1] = v;
    g_wpT[h * EE + e] = v;
}

// ---------------- prep: proj GEMM (32j x 32h tiles, grid 16x16) ----------------
__global__ __launch_bounds__(128) void k_proj(const float* __restrict__ pw,
                                              const float* __restrict__ pb) {
    __shared__ float sA[32][33];
    __shared__ float sB[32][33];
    int t = threadIdx.x;
    int j0 = blockIdx.x * 32, h0 = blockIdx.y * 32;
    int ty = t >> 4, tx = t & 15;
    float acc[4][2] = {};
    for (int kc = 0; kc < DD; kc += 32) {
        __syncthreads();
        int r = t >> 2, c0 = (t & 3) * 8;
        float4 a0 = *(const float4*)(g_s + (size_t)(j0 + r) * DD + kc + c0);
        float4 a1 = *(const float4*)(g_s + (size_t)(j0 + r) * DD + kc + c0 + 4);
        sA[r][c0 + 0] = a0.x; sA[r][c0 + 1] = a0.y; sA[r][c0 + 2] = a0.z; sA[r][c0 + 3] = a0.w;
        sA[r][c0 + 4] = a1.x; sA[r][c0 + 5] = a1.y; sA[r][c0 + 6] = a1.z; sA[r][c0 + 7] = a1.w;
        float4 b0 = *(const float4*)(pw + (size_t)(h0 + r) * DD + kc + c0);
        float4 b1 = *(const float4*)(pw + (size_t)(h0 + r) * DD + kc + c0 + 4);
        sB[r][c0 + 0] = b0.x; sB[r][c0 + 1] = b0.y; sB[r][c0 + 2] = b0.z; sB[r][c0 + 3] = b0.w;
        sB[r][c0 + 4] = b1.x; sB[r][c0 + 5] = b1.y; sB[r][c0 + 6] = b1.z; sB[r][c0 + 7] = b1.w;
        __syncthreads();
        #pragma unroll
        for (int k = 0; k < 32; k++) {
            float bb0 = sB[tx * 2 + 0][k];
            float bb1 = sB[tx * 2 + 1][k];
            #pragma unroll
            for (int m = 0; m < 4; m++) {
                float a = sA[ty * 4 + m][k];
                acc[m][0] += a * bb0;
                acc[m][1] += a * bb1;
            }
        }
    }
    #pragma unroll
    for (int m = 0; m < 4; m++) {
        int j = j0 + ty * 4 + m;
        #pragma unroll
        for (int n = 0; n < 2; n++) {
            int h = h0 + tx * 2 + n;
            __half hv = __float2half(acc[m][n] + pb[h]);
            if (h < HH) g_qh[(size_t)j * HH + h] = hv;
            else        g_kh[(size_t)j * HH + (h - HH)] = hv;
        }
    }
}

// ---------------- prep: Aq / Bk' ----------------
__global__ __launch_bounds__(128) void k_aqbk(const float* __restrict__ ow,
                                              const float* __restrict__ ob) {
    __shared__ float sx[8][256];
    int t = threadIdx.x;
    int r0 = blockIdx.x * 8;
    #pragma unroll
    for (int u = 0; u < 16; u++) {
        int idx = u * 128 + t;
        int rr = idx >> 8, c = idx & 255;
        int gr = r0 + rr;
        const __half* src = (gr < NN) ? (g_qh + (size_t)gr * HH)
                                      : (g_kh + (size_t)(gr - NN) * HH);
        sx[rr][c] = __half2float(src[c]);
    }
    __syncthreads();
    int e = t;
    const float* w = ow + (size_t)e * (2 * HH) + HH;
    float acc[8] = {};
    #pragma unroll 8
    for (int h = 0; h < 256; h += 4) {
        float4 wv = *(const float4*)(w + h);
        #pragma unroll
        for (int rr = 0; rr < 8; rr++) {
            float4 xv = *(const float4*)&sx[rr][h];
            acc[rr] += xv.x * wv.x + xv.y * wv.y + xv.z * wv.z + xv.w * wv.w;
        }
    }
    float obe = ob[e];
    #pragma unroll
    for (int rr = 0; rr < 8; rr++) {
        int gr = r0 + rr;
        if (gr < NN) g_aq[(size_t)gr * EE + e] = acc[rr];
        else         g_bkp[(size_t)(gr - NN) * EE + e] = obe - acc[rr];
    }
}

// ---------------- main kernel ----------------
// tcgen05 layout (bytes from dynamic smem base):
#define SMISC    0                        // tmem ptr @0, mbars @8/16/24/32
#define SB_OFF   1024                     // w_p SW128 image: 65536
#define SQ_OFF   (SB_OFF + 65536)         // q tile: 128 x 528B
#define SAQ_OFF  (SQ_OFF + 67584)         // aq tile: 128 x 528B
#define SK_OFF   (SAQ_OFF + 67584)        // k rows: TI x 512B
#define SBK_OFF  (SK_OFF + TI * 512)      // bk rows: TI x 512B
#define SMEM_TC  (SBK_OFF + TI * 512)     // = 218112

// wmma fallback layout:
#define FB_LDQ 272
#define FB_LDW 144
#define FB_SM_Q 0
#define FB_SM_B (128 * FB_LDQ * 2)
#define FB_SM_A (FB_SM_B + 256 * FB_LDW * 2)
#define FB_SM_K (FB_SM_A + 128 * FB_LDQ * 2)
#define FB_SM_BK (FB_SM_K + 512)
#define SMEM_FB (FB_SM_BK + 16 * 128 * 4)  // 221696

#define SMEM_LAUNCH ((SMEM_TC) > (SMEM_FB) ? (SMEM_TC) : (SMEM_FB))

__global__ __launch_bounds__(256, 1) void k_main(float* __restrict__ out) {
#if HAS_TCGEN05
    extern __shared__ char smem[];
    uint32_t sbase = smem_u32(smem);
    int t = threadIdx.x;
    int w = t >> 5;
    int wg = t >> 7;             // 0 producer WG, 1 consumer WG
    int wt = t & 127;
    int j0 = blockIdx.x * TJ;
    int ibase = blockIdx.y * TI;

    uint32_t mb_mma0 = sbase + 8;
    uint32_t mb_mma1 = sbase + 16;
    uint32_t mb_epi0 = sbase + 24;
    uint32_t mb_epi1 = sbase + 32;

    if (w == 0) {
        TC_ALLOC(sbase + SMISC, 512);
        TC_RELINQ();
    }
    if (t == 0) {
        MBAR_INIT(mb_mma0, 1);
        MBAR_INIT(mb_mma1, 1);
        MBAR_INIT(mb_epi0, 128);
        MBAR_INIT(mb_epi1, 128);
    }
    __syncthreads();
    uint32_t tmem;
    asm volatile("ld.shared.b32 %0, [%1];" : "=r"(tmem) : "r"(sbase + SMISC));

    if (wg == 0) {
        // producer loads: B image, q tile, k rows
        #pragma unroll 4
        for (int u = 0; u < 32; u++) {
            int idx = u * 128 + wt;
            *(int4*)(smem + SB_OFF + idx * 16) = *(const int4*)((const char*)g_wpB + idx * 16);
        }
        #pragma unroll 4
        for (int u = 0; u < 32; u++) {
            int idx = u * 128 + wt;
            int r = idx >> 5, c = idx & 31;
            *(int4*)(smem + SQ_OFF + r * 528 + c * 16) =
                *(const int4*)(g_qh + (size_t)(j0 + r) * HH + c * 8);
        }
        #pragma unroll
        for (int u = 0; u < TI / 4; u++) {
            int idx = u * 128 + wt;          // 0..TI*32-1
            int r = idx >> 5, c = idx & 31;
            *(int4*)(smem + SK_OFF + idx * 16) =
                *(const int4*)(g_kh + (size_t)(ibase + r) * HH + c * 8);
        }
        asm volatile("bar.sync 1, 128;" ::: "memory");

        uint32_t warp_off = (uint32_t)(w << 21);
        uint64_t bbase = make_desc(sbase + SB_OFF);

        for (int i = 0; i < TI; i++) {
            int buf = i & 1;
            uint32_t mb_mma = buf ? mb_mma1 : mb_mma0;
            uint32_t mb_epi = buf ? mb_epi1 : mb_epi0;
            if (i >= 2) { MBAR_WAIT(mb_mma, ((i >> 1) + 1) & 1); }  // A[buf] free

            const __half2* krow = (const __half2*)(smem + SK_OFF + i * 512);
            uint32_t a_st = tmem + 256 + buf * 128 + warp_off;
            #pragma unroll
            for (int cc = 0; cc < 4; cc++) {
                uint32_t regs[32];
                const char* qp = smem + SQ_OFF + wt * 528 + cc * 128;
                #pragma unroll
                for (int u = 0; u < 8; u++) {
                    int4 qv = *(const int4*)(qp + u * 16);
                    const __half2* qh2 = (const __half2*)&qv;
                    #pragma unroll
                    for (int v = 0; v < 4; v++) {
                        __half2 r2 = __hmul2(qh2[v], krow[cc * 32 + u * 4 + v]);
                        regs[u * 4 + v] = *(const uint32_t*)&r2;
                    }
                }
                TC_ST_X32(a_st + cc * 32, regs);
            }
            TC_WAIT_ST();
            TC_FENCE_BEFORE();
            asm volatile("bar.sync 1, 128;" ::: "memory");

            if (w == 0) {
                TC_FENCE_AFTER();
                if (i >= 2) { MBAR_WAIT(mb_epi, ((i >> 1) + 1) & 1); }  // D[buf] free
                if (elect_one()) {
                    uint32_t d_tm = tmem + buf * 128;
                    uint32_t a_tm = tmem + 256 + buf * 128;
                    #pragma unroll
                    for (int s = 0; s < 16; s++) {
                        uint64_t bd = bbase + (uint64_t)((s >> 2) * 1024 + (s & 3) * 2);
                        TC_MMA_F16(d_tm, a_tm + s * 8, bd, IDESC, (s > 0) ? 1u : 0u);
                    }
                    TC_COMMIT(mb_mma);
                }
            }
        }
    } else {
        // consumer loads: aq tile, bk rows
        #pragma unroll 4
        for (int u = 0; u < 32; u++) {
            int idx = u * 128 + wt;
            int r = idx >> 5, c = idx & 31;
            *(int4*)(smem + SAQ_OFF + r * 528 + c * 16) =
                *(const int4*)(g_aq + (size_t)(j0 + r) * EE + c * 4);
        }
        #pragma unroll
        for (int u = 0; u < TI / 4; u++) {
            int idx = u * 128 + wt;
            int r = idx >> 5, c = idx & 31;
            *(int4*)(smem + SBK_OFF + idx * 16) =
                *(const int4*)(g_bkp + (size_t)(ibase + r) * EE + c * 4);
        }
        asm volatile("bar.sync 2, 128;" ::: "memory");

        int row = wt;
        for (int i = 0; i < TI; i++) {
            int buf = i & 1;
            uint32_t mb_mma = buf ? mb_mma1 : mb_mma0;
            uint32_t mb_epi = buf ? mb_epi1 : mb_epi0;
            MBAR_WAIT(mb_mma, (i >> 1) & 1);
            TC_FENCE_AFTER();
            uint32_t d_tm = tmem + buf * 128;
            float* op = out + (((size_t)(ibase + i) * NN + j0 + row) * EE);
            #pragma unroll
            for (int cc = 0; cc < 4; cc++) {
                uint32_t regs[32];
                TC_LD_X32(regs, d_tm + cc * 32);
                TC_WAIT_LD();
                if (cc == 3) { MBAR_ARRIVE(mb_epi); }
                #pragma unroll
                for (int u = 0; u < 8; u++) {
                    float4 a = *(const float4*)(smem + SAQ_OFF + row * 528 + cc * 128 + u * 16);
                    float4 b = *(const float4*)(smem + SBK_OFF + i * 512 + cc * 128 + u * 16);
                    float4 o;
                    o.x = __uint_as_float(regs[u * 4 + 0]) + a.x + b.x;
                    o.y = __uint_as_float(regs[u * 4 + 1]) + a.y + b.y;
                    o.z = __uint_as_float(regs[u * 4 + 2]) + a.z + b.z;
                    o.w = __uint_as_float(regs[u * 4 + 3]) + a.w + b.w;
                    *(float4*)(op + cc * 32 + u * 4) = o;
                }
            }
        }
    }

    __syncthreads();
    if (t == 0) {
        MBAR_INVAL(mb_mma0); MBAR_INVAL(mb_mma1);
        MBAR_INVAL(mb_epi0); MBAR_INVAL(mb_epi1);
    }
    __syncthreads();
    if (w == 0) {
        TC_DEALLOC(tmem, 512);
    }
#else
    // -------- wmma fallback (family-generic pass; known-correct round-2 body) --------
    using namespace nvcuda;
    extern __shared__ char smem_raw[];
    __half* sQ  = (__half*)(smem_raw + FB_SM_Q);
    __half* sB  = (__half*)(smem_raw + FB_SM_B);
    __half* sA  = (__half*)(smem_raw + FB_SM_A);
    __half* sK  = (__half*)(smem_raw + FB_SM_K);
    float*  sBk = (float*)(smem_raw + FB_SM_BK);

    int t = threadIdx.x;
    int w = t >> 5;
    int wj = w >> 1;
    int we = w & 1;
    int j0 = blockIdx.x * TJ;
    int ibase = blockIdx.y * TI;

    for (int idx = t; idx < 4096; idx += 256) {
        int r = idx >> 5, c = idx & 31;
        *(int4*)(sQ + r * FB_LDQ + c * 8) = *(const int4*)(g_qh + (size_t)(j0 + r) * HH + c * 8);
    }
    for (int idx = t; idx < 4096; idx += 256) {
        int r = idx >> 4, c = idx & 15;
        *(int4*)(sB + r * FB_LDW + c * 8) = *(const int4*)(g_wpT + (size_t)r * EE + c * 8);
    }

    for (int it = 0; it < TI; it++) {
        int i = ibase + it;
        if (t < 32) *(int4*)(sK + t * 8) = *(const int4*)(g_kh + (size_t)i * HH + t * 8);
        {
            const float4* src = (const float4*)(g_bkp + (size_t)i * EE);
            #pragma unroll
            for (int idx = t; idx < 512; idx += 256) {
                int c = idx & 31;
                ((float4*)sBk)[idx] = src[c];
            }
        }
        __syncthreads();

        for (int idx = t; idx < 4096; idx += 256) {
            int r = idx >> 5, c = idx & 31;
            int4 qv = *(const int4*)(sQ + r * FB_LDQ + c * 8);
            int4 kv = *(const int4*)(sK + c * 8);
            const __half2* qh2 = (const __half2*)&qv;
            const __half2* kh2 = (const __half2*)&kv;
            int4 av;
            __half2* ah = (__half2*)&av;
            ah[0] = __hmul2(qh2[0], kh2[0]);
            ah[1] = __hmul2(qh2[1], kh2[1]);
            ah[2] = __hmul2(qh2[2], kh2[2]);
            ah[3] = __hmul2(qh2[3], kh2[3]);
            *(int4*)(sA + r * FB_LDQ + c * 8) = av;
        }
        __syncthreads();

        wmma::fragment<wmma::accumulator, 16, 16, 16, float> acc[2][4];
        #pragma unroll
        for (int m = 0; m < 2; m++)
            #pragma unroll
            for (int n = 0; n < 4; n++)
                wmma::fill_fragment(acc[m][n], 0.0f);

        #pragma unroll
        for (int kk = 0; kk < HH; kk += 16) {
            wmma::fragment<wmma::matrix_a, 16, 16, 16, __half, wmma::row_major> af[2];
            wmma::fragment<wmma::matrix_b, 16, 16, 16, __half, wmma::row_major> bf[4];
            #pragma unroll
            for (int m = 0; m < 2; m++)
                wmma::load_matrix_sync(af[m], sA + (wj * 32 + m * 16) * FB_LDQ + kk, FB_LDQ);
            #pragma unroll
            for (int n = 0; n < 4; n++)
                wmma::load_matrix_sync(bf[n], sB + kk * FB_LDW + we * 64 + n * 16, FB_LDW);
            #pragma unroll
            for (int m = 0; m < 2; m++)
                #pragma unroll
                for (int n = 0; n < 4; n++)
                    wmma::mma_sync(acc[m][n], af[m], bf[n], acc[m][n]);
        }

        #pragma unroll
        for (int m = 0; m < 2; m++) {
            int jr = j0 + wj * 32 + m * 16;
            #pragma unroll
            for (int n = 0; n < 4; n++) {
                int ec = we * 64 + n * 16;
                wmma::fragment<wmma::accumulator, 16, 16, 16, float> aqf, bkf;
                wmma::load_matrix_sync(aqf, g_aq + (size_t)jr * EE + ec, EE, wmma::mem_row_major);
                wmma::load_matrix_sync(bkf, sBk + ec, 128, wmma::mem_row_major);
                #pragma unroll
                for (int u = 0; u < acc[m][n].num_elements; u++)
                    acc[m][n].x[u] += aqf.x[u] + bkf.x[u];
                wmma::store_matrix_sync(out + ((size_t)i * NN + jr) * EE + ec,
                                        acc[m][n], EE, wmma::mem_row_major);
            }
        }
        __syncthreads();
    }
#endif
}

// ---------------- launcher ----------------
extern "C" void kernel_launch(void* const* d_in, const int* in_sizes, int n_in,
                              void* d_out, int out_size) {
    const float* node = (const float*)d_in[0];
    const float* ln_w = (const float*)d_in[1];
    const float* ln_b = (const float*)d_in[2];
    const float* pw   = (const float*)d_in[3];
    const float* pb   = (const float*)d_in[4];
    const float* ow   = (const float*)d_in[5];
    const float* ob   = (const float*)d_in[6];
    float* out = (float*)d_out;

    cudaFuncSetAttribute(k_main, cudaFuncAttributeMaxDynamicSharedMemorySize, SMEM_LAUNCH);

    k_ln<<<NN, 256>>>(node, ln_w, ln_b);
    k_wp<<<128, 256>>>(ow);
    {
        dim3 g(NN / 32, (2 * HH) / 32);
        k_proj<<<g, 128>>>(pw, pb);
    }
    k_aqbk<<<2 * NN / 8, 128>>>(ow, ob);
    {
        dim3 g(NN / TJ, NN / TI);
        k_main<<<g, 256, SMEM_LAUNCH>>>(out);
    }
}